// round 1
// baseline (speedup 1.0000x reference)
#include <cuda_runtime.h>
#include <cuda_bf16.h>
#include <cstdint>

// Problem constants
#define M_ROWS 16384          // B_SZ * SEQ
#define K_IN   4096           // D_IN
#define N_OUT  4096           // D_OUT
#define R_LORA 64
#define K_TOP  16
#define K_EXT  4160           // K_IN + R_LORA
#define SCALE_F 2.0f          // ALPHA / R

// Scratch (device globals: allocation-free)
__device__ float g_xe[(size_t)M_ROWS * K_EXT];   // tf32-rounded x  ||  scaled sparse z
__device__ float g_we[(size_t)N_OUT * K_EXT];    // tf32-rounded W  ||  tf32 B
__device__ float g_zp[4ull * M_ROWS * R_LORA];   // split-K partials of z (fp32)

__device__ __forceinline__ float tf32r(float x) {
    uint32_t u;
    asm("cvt.rna.tf32.f32 %0, %1;" : "=r"(u) : "f"(x));
    return __uint_as_float(u);
}

// ---------------------------------------------------------------------------
// Conversion kernels: fp32 -> tf32(RNA) into the K-extended scratch matrices
// ---------------------------------------------------------------------------
__global__ void cvt_x_kernel(const float4* __restrict__ in) {
    int i = blockIdx.x * 256 + threadIdx.x;        // 16,777,216 float4s exactly
    int r = i >> 10;                                // row (1024 float4 per row)
    int c = i & 1023;
    float4 v = in[i];
    v.x = tf32r(v.x); v.y = tf32r(v.y); v.z = tf32r(v.z); v.w = tf32r(v.w);
    *(float4*)&g_xe[(size_t)r * K_EXT + (c << 2)] = v;
}

__global__ void cvt_w_kernel(const float4* __restrict__ in) {
    int i = blockIdx.x * 256 + threadIdx.x;        // 4,194,304 float4s exactly
    int r = i >> 10;
    int c = i & 1023;
    float4 v = in[i];
    v.x = tf32r(v.x); v.y = tf32r(v.y); v.z = tf32r(v.z); v.w = tf32r(v.w);
    *(float4*)&g_we[(size_t)r * K_EXT + (c << 2)] = v;
}

__global__ void cvt_b_kernel(const float4* __restrict__ in) {
    int i = blockIdx.x * 256 + threadIdx.x;        // 65,536 float4s (4096 x 64)
    int r = i >> 4;                                 // 16 float4 per row
    int c = i & 15;
    float4 v = in[i];
    v.x = tf32r(v.x); v.y = tf32r(v.y); v.z = tf32r(v.z); v.w = tf32r(v.w);
    *(float4*)&g_we[(size_t)r * K_EXT + K_IN + (c << 2)] = v;
}

// ---------------------------------------------------------------------------
// z = x @ A^T in fp32 (accuracy needed for correct top-k selection).
// Split-K=4 with separate partial buffers (deterministic, no atomics).
// Block: 128 threads, tile 128(m) x 64(r), each thread 8x8 accumulators.
// ---------------------------------------------------------------------------
__global__ __launch_bounds__(128) void z_partial(const float* __restrict__ x,
                                                 const float* __restrict__ Amat) {
    __shared__ float xsT[32][132];   // [k][m], stride 132 (16B-aligned rows)
    __shared__ float asT[32][68];    // [k][r]

    const int t  = threadIdx.x;
    const int m0 = blockIdx.x * 128;
    const int kb = blockIdx.y * 1024;
    const int tm = t >> 3;           // 0..15  -> m block of 8
    const int tr = t & 7;            // 0..7   -> r block of 8

    float acc[8][8];
#pragma unroll
    for (int i = 0; i < 8; i++)
#pragma unroll
        for (int j = 0; j < 8; j++) acc[i][j] = 0.0f;

    for (int kc = 0; kc < 1024; kc += 32) {
        const int k0 = kb + kc;
        const int kk0 = (t & 7) << 2;
        // load x tile 128 x 32 (transposed into smem)
#pragma unroll
        for (int i = 0; i < 8; i++) {
            int r = (t >> 3) + i * 16;
            float4 v = *(const float4*)&x[(size_t)(m0 + r) * K_IN + k0 + kk0];
            xsT[kk0 + 0][r] = v.x; xsT[kk0 + 1][r] = v.y;
            xsT[kk0 + 2][r] = v.z; xsT[kk0 + 3][r] = v.w;
        }
        // load A tile 64 x 32 (transposed)
#pragma unroll
        for (int i = 0; i < 4; i++) {
            int r = (t >> 3) + i * 16;
            float4 v = *(const float4*)&Amat[(size_t)r * K_IN + k0 + kk0];
            asT[kk0 + 0][r] = v.x; asT[kk0 + 1][r] = v.y;
            asT[kk0 + 2][r] = v.z; asT[kk0 + 3][r] = v.w;
        }
        __syncthreads();
#pragma unroll
        for (int kk = 0; kk < 32; kk++) {
            float av[8], bv[8];
            *(float4*)&av[0] = *(const float4*)&xsT[kk][tm * 8];
            *(float4*)&av[4] = *(const float4*)&xsT[kk][tm * 8 + 4];
            *(float4*)&bv[0] = *(const float4*)&asT[kk][tr * 8];
            *(float4*)&bv[4] = *(const float4*)&asT[kk][tr * 8 + 4];
#pragma unroll
            for (int i = 0; i < 8; i++)
#pragma unroll
                for (int j = 0; j < 8; j++)
                    acc[i][j] = fmaf(av[i], bv[j], acc[i][j]);
        }
        __syncthreads();
    }

    float* zp = g_zp + (size_t)blockIdx.y * M_ROWS * R_LORA;
#pragma unroll
    for (int i = 0; i < 8; i++)
#pragma unroll
        for (int j = 0; j < 8; j++)
            zp[(size_t)(m0 + tm * 8 + i) * R_LORA + tr * 8 + j] = acc[i][j];
}

// ---------------------------------------------------------------------------
// Top-k (k=16 of 64): keep iff #{j: az_j > az_i} < 16  (== az >= thresh incl. ties)
// Writes SCALE * z (tf32-rounded) into the K-extension columns of g_xe.
// ---------------------------------------------------------------------------
__global__ void topk_kernel() {
    __shared__ float az[4][64];
    const int sub = threadIdx.x >> 6;
    const int j   = threadIdx.x & 63;
    const int row = blockIdx.x * 4 + sub;

    const size_t ZP = (size_t)M_ROWS * R_LORA;
    const size_t base = (size_t)row * R_LORA + j;
    float v = ((g_zp[base] + g_zp[base + ZP]) + g_zp[base + 2 * ZP]) + g_zp[base + 3 * ZP];
    float a = fabsf(v);
    az[sub][j] = a;
    __syncthreads();

    int cnt = 0;
#pragma unroll
    for (int t = 0; t < 64; t++) cnt += (az[sub][t] > a) ? 1 : 0;

    g_xe[(size_t)row * K_EXT + K_IN + j] = (cnt < K_TOP) ? tf32r(v * SCALE_F) : 0.0f;
}

// ---------------------------------------------------------------------------
// Main GEMM: out[m,n] = sum_{k<4160} xe[m,k] * we[n,k] + bias[n]
// tf32 mma.sync m16n8k8, 128x128x32 tiles, 3-stage cp.async pipeline.
// ---------------------------------------------------------------------------
#define BM 128
#define BN 128
#define BK 32
#define NSTAGE 3
#define LDA_S 36                       // smem row stride (floats), conflict-free
#define KTILES (K_EXT / BK)            // 130
#define STAGE_BYTES (BM * LDA_S * 4)

__device__ __forceinline__ void cp_async16(uint32_t smem_addr, const void* gptr) {
    asm volatile("cp.async.cg.shared.global [%0], [%1], 16;\n"
                 :: "r"(smem_addr), "l"(gptr));
}

__device__ __forceinline__ void mma_tf32(float* c, const uint32_t* a, const uint32_t* b) {
    asm volatile(
        "mma.sync.aligned.m16n8k8.row.col.f32.tf32.tf32.f32 "
        "{%0,%1,%2,%3}, {%4,%5,%6,%7}, {%8,%9}, {%0,%1,%2,%3};\n"
        : "+f"(c[0]), "+f"(c[1]), "+f"(c[2]), "+f"(c[3])
        : "r"(a[0]), "r"(a[1]), "r"(a[2]), "r"(a[3]), "r"(b[0]), "r"(b[1]));
}

__global__ __launch_bounds__(256, 1) void gemm_kernel(const float* __restrict__ bias,
                                                      float* __restrict__ out) {
    extern __shared__ float sm[];
    float* As = sm;
    float* Bs = sm + NSTAGE * BM * LDA_S;

    const int t = threadIdx.x;

    // L2-friendly block rasterization (groups of 8 m-tiles)
    int pid = blockIdx.x;
    const int num_n = N_OUT / BN;      // 32
    const int GRP = 8;
    const int ppg = GRP * num_n;       // 256
    int grp = pid / ppg;
    int bm = grp * GRP + ((pid % ppg) % GRP);
    int bn = (pid % ppg) / GRP;

    // cp.async thread mapping: 32 rows x 8 float4-cols per pass, 4 passes
    const int lr = t >> 3;             // 0..31
    const int lc = t & 7;              // 0..7
    const float* agp = g_xe + (size_t)(bm * BM + lr) * K_EXT + lc * 4;
    const float* bgp = g_we + (size_t)(bn * BN + lr) * K_EXT + lc * 4;
    const uint32_t sAb = (uint32_t)__cvta_generic_to_shared(As) + (lr * LDA_S + lc * 4) * 4;
    const uint32_t sBb = (uint32_t)__cvta_generic_to_shared(Bs) + (lr * LDA_S + lc * 4) * 4;

    // prologue: stages 0..NSTAGE-2
#pragma unroll
    for (int s = 0; s < NSTAGE - 1; s++) {
#pragma unroll
        for (int i = 0; i < 4; i++) {
            cp_async16(sAb + s * STAGE_BYTES + i * 32 * LDA_S * 4,
                       agp + (size_t)i * 32 * K_EXT + s * BK);
            cp_async16(sBb + s * STAGE_BYTES + i * 32 * LDA_S * 4,
                       bgp + (size_t)i * 32 * K_EXT + s * BK);
        }
        asm volatile("cp.async.commit_group;\n");
    }

    const int lane = t & 31, warp = t >> 5;
    const int wm = warp & 1;           // 2 warps in m  -> 64-row warp tile
    const int wn = warp >> 1;          // 4 warps in n  -> 32-col warp tile
    const int gr = lane >> 2, tg = lane & 3;

    float c[4][4][4];
#pragma unroll
    for (int mf = 0; mf < 4; mf++)
#pragma unroll
        for (int nf = 0; nf < 4; nf++)
#pragma unroll
            for (int q = 0; q < 4; q++) c[mf][nf][q] = 0.0f;

    for (int kt = 0; kt < KTILES; kt++) {
        asm volatile("cp.async.wait_group 1;\n");
        __syncthreads();

        const int kf = kt + NSTAGE - 1;
        if (kf < KTILES) {
            const int buf = kf % NSTAGE;
#pragma unroll
            for (int i = 0; i < 4; i++) {
                cp_async16(sAb + buf * STAGE_BYTES + i * 32 * LDA_S * 4,
                           agp + (size_t)i * 32 * K_EXT + kf * BK);
                cp_async16(sBb + buf * STAGE_BYTES + i * 32 * LDA_S * 4,
                           bgp + (size_t)i * 32 * K_EXT + kf * BK);
            }
        }
        asm volatile("cp.async.commit_group;\n");

        const float* Ab = As + (kt % NSTAGE) * BM * LDA_S;
        const float* Bb = Bs + (kt % NSTAGE) * BM * LDA_S;

#pragma unroll
        for (int ks = 0; ks < 4; ks++) {
            uint32_t a[4][4], b[4][2];
#pragma unroll
            for (int mf = 0; mf < 4; mf++) {
                const float* p = Ab + (wm * 64 + mf * 16 + gr) * LDA_S + ks * 8 + tg;
                a[mf][0] = __float_as_uint(p[0]);
                a[mf][1] = __float_as_uint(p[8 * LDA_S]);
                a[mf][2] = __float_as_uint(p[4]);
                a[mf][3] = __float_as_uint(p[8 * LDA_S + 4]);
            }
#pragma unroll
            for (int nf = 0; nf < 4; nf++) {
                const float* p = Bb + (wn * 32 + nf * 8 + gr) * LDA_S + ks * 8 + tg;
                b[nf][0] = __float_as_uint(p[0]);
                b[nf][1] = __float_as_uint(p[4]);
            }
#pragma unroll
            for (int mf = 0; mf < 4; mf++)
#pragma unroll
                for (int nf = 0; nf < 4; nf++)
                    mma_tf32(c[mf][nf], a[mf], b[nf]);
        }
    }

    // epilogue: add bias, write fp32
#pragma unroll
    for (int mf = 0; mf < 4; mf++) {
        const int row = bm * BM + wm * 64 + mf * 16 + gr;
#pragma unroll
        for (int nf = 0; nf < 4; nf++) {
            const int col = bn * BN + wn * 32 + nf * 8 + tg * 2;
            const float b0 = __ldg(&bias[col]);
            const float b1 = __ldg(&bias[col + 1]);
            float2 v0 = make_float2(c[mf][nf][0] + b0, c[mf][nf][1] + b1);
            float2 v1 = make_float2(c[mf][nf][2] + b0, c[mf][nf][3] + b1);
            *(float2*)&out[(size_t)row * N_OUT + col] = v0;
            *(float2*)&out[(size_t)(row + 8) * N_OUT + col] = v1;
        }
    }
}

// ---------------------------------------------------------------------------
extern "C" void kernel_launch(void* const* d_in, const int* in_sizes, int n_in,
                              void* d_out, int out_size) {
    const float* x    = (const float*)d_in[0];
    const float* W    = (const float*)d_in[1];
    const float* bias = (const float*)d_in[2];
    const float* A    = (const float*)d_in[3];
    const float* Bm   = (const float*)d_in[4];
    float* out = (float*)d_out;

    cudaFuncSetAttribute(gemm_kernel, cudaFuncAttributeMaxDynamicSharedMemorySize,
                         NSTAGE * BM * LDA_S * 4 * 2);

    cvt_x_kernel<<<65536, 256>>>((const float4*)x);
    cvt_w_kernel<<<16384, 256>>>((const float4*)W);
    cvt_b_kernel<<<256, 256>>>((const float4*)Bm);
    z_partial<<<dim3(128, 4), 128>>>(x, A);
    topk_kernel<<<4096, 256>>>();
    gemm_kernel<<<4096, 256, NSTAGE * BM * LDA_S * 4 * 2>>>(bias, out);
}

// round 8
// speedup vs baseline: 1.1984x; 1.1984x over previous
#include <cuda_runtime.h>
#include <cuda_bf16.h>
#include <cstdint>

// Problem constants
#define M_ROWS 16384          // B_SZ * SEQ
#define K_IN   4096           // D_IN
#define N_OUT  4096           // D_OUT
#define R_LORA 64
#define K_TOP  16
#define K_EXT  4160           // K_IN + R_LORA
#define SCALE_F 2.0f          // ALPHA / R
#define KB8    (K_EXT / 8)    // 520 k-blocks of 8

// GEMM tiling
#define BM 128
#define BN 256
#define NSTAGE 3
#define KTILES (K_EXT / 32)        // 130
#define A_ST_BYTES 16384           // 8 mt * 4 kb * 512B
#define B_ST_BYTES 32768           // 16 nt * 4 kb * 512B
#define STAGE_BYTES (A_ST_BYTES + B_ST_BYTES)   // 49152
#define GRID_TILES ((M_ROWS / BM) * (N_OUT / BN))   // 128*16 = 2048

// Scratch (device globals: allocation-free).
// g_xe: fragment-major tf32 A' :  [mt(1024)][kb(520)][lane(32)] float4 = (a0,a1,a2,a3)
//   a0=A[mt*16+gr][kb*8+tg] a1=[gr+8][tg] a2=[gr][tg+4] a3=[gr+8][tg+4], gr=lane>>2, tg=lane&3
// g_we: fragment-major tf32 B' :  [nt(256)][kb(520)][lane] float4 = (b(gr,tg), b(gr,tg+4), b(gr+8,tg), b(gr+8,tg+4))
__device__ float g_xe[(size_t)M_ROWS * K_EXT];
__device__ float g_we[(size_t)N_OUT * K_EXT];
__device__ float g_zp[4ull * M_ROWS * R_LORA];   // split-K partials of z (fp32)

__device__ __forceinline__ float tf32r(float x) {
    uint32_t u;
    asm("cvt.rna.tf32.f32 %0, %1;" : "=r"(u) : "f"(x));
    return __uint_as_float(u);
}

// ---------------------------------------------------------------------------
// cvt_x: fp32 x -> tf32, permuted into g_xe fragment layout (k < 4096 region)
// block = one mt (16 rows) x 256 k.  grid = 1024 * 16
// ---------------------------------------------------------------------------
__global__ __launch_bounds__(256) void cvt_x_kernel(const float4* __restrict__ in) {
    __shared__ float s[16][260];
    const int t  = threadIdx.x;
    const int mt = blockIdx.x >> 4;
    const int kc = blockIdx.x & 15;

    // read phase: coalesced float4 loads, tf32 round, store to smem
#pragma unroll
    for (int p = 0; p < 4; p++) {
        int idx = t + p * 256;              // 0..1023
        int row = idx >> 6;                 // 0..15
        int kq  = idx & 63;                 // float4 within 256-k chunk
        float4 v = in[((size_t)(mt * 16 + row) * K_IN + kc * 256) / 4 + kq];
        s[row][kq * 4 + 0] = tf32r(v.x);
        s[row][kq * 4 + 1] = tf32r(v.y);
        s[row][kq * 4 + 2] = tf32r(v.z);
        s[row][kq * 4 + 3] = tf32r(v.w);
    }
    __syncthreads();

    // gather phase: write fragment-major float4, coalesced
    float4* g4 = (float4*)g_xe;
#pragma unroll
    for (int p = 0; p < 4; p++) {
        int idx  = t + p * 256;
        int kbl  = idx >> 5;                // 0..31 (k-block of 8 within 256)
        int lane = idx & 31;
        int gr = lane >> 2, tg = lane & 3;
        int kk = kbl * 8;
        float4 v;
        v.x = s[gr    ][kk + tg    ];
        v.y = s[gr + 8][kk + tg    ];
        v.z = s[gr    ][kk + tg + 4];
        v.w = s[gr + 8][kk + tg + 4];
        g4[((size_t)mt * KB8 + kc * 32 + kbl) * 32 + lane] = v;
    }
}

// ---------------------------------------------------------------------------
// cvt_w: fp32 W -> tf32, permuted into g_we fragment layout (k < 4096 region)
// block = one nt (16 rows) x 256 k.  grid = 256 * 16
// ---------------------------------------------------------------------------
__global__ __launch_bounds__(256) void cvt_w_kernel(const float4* __restrict__ in) {
    __shared__ float s[16][260];
    const int t  = threadIdx.x;
    const int nt = blockIdx.x >> 4;
    const int kc = blockIdx.x & 15;

#pragma unroll
    for (int p = 0; p < 4; p++) {
        int idx = t + p * 256;
        int row = idx >> 6;
        int kq  = idx & 63;
        float4 v = in[((size_t)(nt * 16 + row) * K_IN + kc * 256) / 4 + kq];
        s[row][kq * 4 + 0] = tf32r(v.x);
        s[row][kq * 4 + 1] = tf32r(v.y);
        s[row][kq * 4 + 2] = tf32r(v.z);
        s[row][kq * 4 + 3] = tf32r(v.w);
    }
    __syncthreads();

    float4* g4 = (float4*)g_we;
#pragma unroll
    for (int p = 0; p < 4; p++) {
        int idx  = t + p * 256;
        int kbl  = idx >> 5;
        int lane = idx & 31;
        int gr = lane >> 2, tg = lane & 3;
        int kk = kbl * 8;
        float4 v;
        v.x = s[gr    ][kk + tg    ];
        v.y = s[gr    ][kk + tg + 4];
        v.z = s[gr + 8][kk + tg    ];
        v.w = s[gr + 8][kk + tg + 4];
        g4[((size_t)nt * KB8 + kc * 32 + kbl) * 32 + lane] = v;
    }
}

// ---------------------------------------------------------------------------
// cvt_b: LoRA B (4096 x 64) -> tf32, into g_we extension region (kb 512..519)
// block = 4 nt tiles (64 rows) x 64 k.  grid = 64
// ---------------------------------------------------------------------------
__global__ __launch_bounds__(256) void cvt_b_kernel(const float4* __restrict__ in) {
    __shared__ float s[64][68];
    const int t  = threadIdx.x;
    const int n0t = blockIdx.x * 4;     // first nt tile

#pragma unroll
    for (int p = 0; p < 4; p++) {
        int idx = t + p * 256;          // 0..1023 float4s (64 rows x 16)
        int row = idx >> 4;
        int kq  = idx & 15;
        float4 v = in[((size_t)(n0t * 16 + row) * R_LORA) / 4 + kq];
        s[row][kq * 4 + 0] = tf32r(v.x);
        s[row][kq * 4 + 1] = tf32r(v.y);
        s[row][kq * 4 + 2] = tf32r(v.z);
        s[row][kq * 4 + 3] = tf32r(v.w);
    }
    __syncthreads();

    float4* g4 = (float4*)g_we;
#pragma unroll
    for (int p = 0; p < 4; p++) {
        int idx  = t + p * 256;
        int b2   = idx >> 5;            // 0..31: ntl*8 + kbl
        int ntl  = b2 >> 3;
        int kbl  = b2 & 7;
        int lane = idx & 31;
        int gr = lane >> 2, tg = lane & 3;
        int r0 = ntl * 16;
        int kk = kbl * 8;
        float4 v;
        v.x = s[r0 + gr    ][kk + tg    ];
        v.y = s[r0 + gr    ][kk + tg + 4];
        v.z = s[r0 + gr + 8][kk + tg    ];
        v.w = s[r0 + gr + 8][kk + tg + 4];
        g4[((size_t)(n0t + ntl) * KB8 + 512 + kbl) * 32 + lane] = v;
    }
}

// ---------------------------------------------------------------------------
// z = x @ A^T in fp32 (accuracy needed for correct top-k selection).
// Split-K=4, deterministic partial buffers.
// ---------------------------------------------------------------------------
__global__ __launch_bounds__(128) void z_partial(const float* __restrict__ x,
                                                 const float* __restrict__ Amat) {
    __shared__ float xsT[32][132];
    __shared__ float asT[32][68];

    const int t  = threadIdx.x;
    const int m0 = blockIdx.x * 128;
    const int kb = blockIdx.y * 1024;
    const int tm = t >> 3;
    const int tr = t & 7;

    float acc[8][8];
#pragma unroll
    for (int i = 0; i < 8; i++)
#pragma unroll
        for (int j = 0; j < 8; j++) acc[i][j] = 0.0f;

    for (int kc = 0; kc < 1024; kc += 32) {
        const int k0 = kb + kc;
        const int kk0 = (t & 7) << 2;
#pragma unroll
        for (int i = 0; i < 8; i++) {
            int r = (t >> 3) + i * 16;
            float4 v = *(const float4*)&x[(size_t)(m0 + r) * K_IN + k0 + kk0];
            xsT[kk0 + 0][r] = v.x; xsT[kk0 + 1][r] = v.y;
            xsT[kk0 + 2][r] = v.z; xsT[kk0 + 3][r] = v.w;
        }
#pragma unroll
        for (int i = 0; i < 4; i++) {
            int r = (t >> 3) + i * 16;
            float4 v = *(const float4*)&Amat[(size_t)r * K_IN + k0 + kk0];
            asT[kk0 + 0][r] = v.x; asT[kk0 + 1][r] = v.y;
            asT[kk0 + 2][r] = v.z; asT[kk0 + 3][r] = v.w;
        }
        __syncthreads();
#pragma unroll
        for (int kk = 0; kk < 32; kk++) {
            float av[8], bv[8];
            *(float4*)&av[0] = *(const float4*)&xsT[kk][tm * 8];
            *(float4*)&av[4] = *(const float4*)&xsT[kk][tm * 8 + 4];
            *(float4*)&bv[0] = *(const float4*)&asT[kk][tr * 8];
            *(float4*)&bv[4] = *(const float4*)&asT[kk][tr * 8 + 4];
#pragma unroll
            for (int i = 0; i < 8; i++)
#pragma unroll
                for (int j = 0; j < 8; j++)
                    acc[i][j] = fmaf(av[i], bv[j], acc[i][j]);
        }
        __syncthreads();
    }

    float* zp = g_zp + (size_t)blockIdx.y * M_ROWS * R_LORA;
#pragma unroll
    for (int i = 0; i < 8; i++)
#pragma unroll
        for (int j = 0; j < 8; j++)
            zp[(size_t)(m0 + tm * 8 + i) * R_LORA + tr * 8 + j] = acc[i][j];
}

// ---------------------------------------------------------------------------
// Top-k (k=16 of 64): keep iff #{j: az_j > az_i} < 16.
// Writes SCALE*z (tf32) into the fragment-major extension block of g_xe.
// ---------------------------------------------------------------------------
__global__ void topk_kernel() {
    __shared__ float az[4][64];
    const int sub = threadIdx.x >> 6;
    const int j   = threadIdx.x & 63;
    const int row = blockIdx.x * 4 + sub;

    const size_t ZP = (size_t)M_ROWS * R_LORA;
    const size_t base = (size_t)row * R_LORA + j;
    float v = ((g_zp[base] + g_zp[base + ZP]) + g_zp[base + 2 * ZP]) + g_zp[base + 3 * ZP];
    float a = fabsf(v);
    az[sub][j] = a;
    __syncthreads();

    int cnt = 0;
#pragma unroll
    for (int t = 0; t < 64; t++) cnt += (az[sub][t] > a) ? 1 : 0;

    // fragment-major address within g_xe (A' layout)
    size_t fi = (((size_t)(row >> 4) * KB8 + 512 + (j >> 3)) * 32
                 + (row & 7) * 4 + (j & 3)) * 4
                + ((row >> 3) & 1) + (((j >> 2) & 1) << 1);
    g_xe[fi] = (cnt < K_TOP) ? tf32r(v * SCALE_F) : 0.0f;
}

// ---------------------------------------------------------------------------
// Main GEMM: out[m,n] = sum_k xe*we + bias.  tf32 mma.sync m16n8k8.
// CTA 128x256x32, warp tile 64x64, fragment-major smem, LDS.128 only.
// ---------------------------------------------------------------------------
__device__ __forceinline__ void cp_async16(uint32_t smem_addr, const void* gptr) {
    asm volatile("cp.async.cg.shared.global [%0], [%1], 16;\n"
                 :: "r"(smem_addr), "l"(gptr));
}

__device__ __forceinline__ void mma4(float* c, const float4& a, float b0, float b1) {
    asm volatile(
        "mma.sync.aligned.m16n8k8.row.col.f32.tf32.tf32.f32 "
        "{%0,%1,%2,%3}, {%4,%5,%6,%7}, {%8,%9}, {%0,%1,%2,%3};\n"
        : "+f"(c[0]), "+f"(c[1]), "+f"(c[2]), "+f"(c[3])
        : "r"(__float_as_uint(a.x)), "r"(__float_as_uint(a.y)),
          "r"(__float_as_uint(a.z)), "r"(__float_as_uint(a.w)),
          "r"(__float_as_uint(b0)), "r"(__float_as_uint(b1)));
}

__global__ __launch_bounds__(256, 1) void gemm_kernel(const float* __restrict__ bias,
                                                      float* __restrict__ out) {
    extern __shared__ float4 sm4[];

    const int t    = threadIdx.x;
    const int lane = t & 31;
    const int wid  = t >> 5;
    const int wm   = wid & 1;          // 2 warps in m (64 rows each)
    const int wn   = wid >> 1;         // 4 warps in n (64 cols each)

    // L2-friendly rasterization: supertiles of 8 bm x 16 bn
    const int pid = blockIdx.x;
    const int grp = pid >> 7;                // 0..15
    const int loc = pid & 127;
    const int bm  = grp * 8 + (loc & 7);     // 0..127
    const int bn  = loc >> 3;                // 0..15

    const float4* gA = (const float4*)g_xe;
    const float4* gB = (const float4*)g_we;
    const uint32_t sbase = (uint32_t)__cvta_generic_to_shared(sm4);

    // per-thread cp.async chunk descriptors (kt=0 global float4 index, smem offset)
    size_t aG[4]; uint32_t aS[4];
#pragma unroll
    for (int i = 0; i < 4; i++) {
        int ia   = t + i * 256;              // 0..1023
        int blk  = ia >> 5;                  // mtl*4 + kbl
        int lc   = ia & 31;
        int mtl  = blk >> 2, kbl = blk & 3;
        aG[i] = ((size_t)(bm * 8 + mtl) * KB8 + kbl) * 32 + lc;
        aS[i] = (uint32_t)(ia * 16);
    }
    size_t bG[8]; uint32_t bS[8];
#pragma unroll
    for (int i = 0; i < 8; i++) {
        int ib   = t + i * 256;              // 0..2047
        int blk  = ib >> 5;                  // ntl*4 + kbl
        int lc   = ib & 31;
        int ntl  = blk >> 2, kbl = blk & 3;
        bG[i] = ((size_t)(bn * 16 + ntl) * KB8 + kbl) * 32 + lc;
        bS[i] = (uint32_t)(A_ST_BYTES + ib * 16);
    }

    // prologue: stages 0..1
#pragma unroll
    for (int s = 0; s < NSTAGE - 1; s++) {
        uint32_t so = sbase + s * STAGE_BYTES;
#pragma unroll
        for (int i = 0; i < 4; i++) cp_async16(so + aS[i], gA + aG[i] + (size_t)s * 128);
#pragma unroll
        for (int i = 0; i < 8; i++) cp_async16(so + bS[i], gB + bG[i] + (size_t)s * 128);
        asm volatile("cp.async.commit_group;\n");
    }

    float c[4][8][4];
#pragma unroll
    for (int mf = 0; mf < 4; mf++)
#pragma unroll
        for (int nf = 0; nf < 8; nf++)
#pragma unroll
            for (int q = 0; q < 4; q++) c[mf][nf][q] = 0.0f;

    for (int kt = 0; kt < KTILES; kt++) {
        asm volatile("cp.async.wait_group 1;\n");
        __syncthreads();

        const int kf = kt + NSTAGE - 1;
        if (kf < KTILES) {
            uint32_t so = sbase + (kf % NSTAGE) * STAGE_BYTES;
#pragma unroll
            for (int i = 0; i < 4; i++) cp_async16(so + aS[i], gA + aG[i] + (size_t)kf * 128);
#pragma unroll
            for (int i = 0; i < 8; i++) cp_async16(so + bS[i], gB + bG[i] + (size_t)kf * 128);
        }
        asm volatile("cp.async.commit_group;\n");

        const float4* As4 = sm4 + (size_t)(kt % NSTAGE) * (STAGE_BYTES / 16);
        const float4* Bs4 = As4 + (A_ST_BYTES / 16);

#pragma unroll
        for (int ks = 0; ks < 4; ks++) {
            float4 af[4], bf[4];
#pragma unroll
            for (int mf = 0; mf < 4; mf++)
                af[mf] = As4[((wm * 4 + mf) * 4 + ks) * 32 + lane];
#pragma unroll
            for (int np = 0; np < 4; np++)
                bf[np] = Bs4[((wn * 4 + np) * 4 + ks) * 32 + lane];
#pragma unroll
            for (int mf = 0; mf < 4; mf++)
#pragma unroll
                for (int np = 0; np < 4; np++) {
                    mma4(c[mf][2 * np],     af[mf], bf[np].x, bf[np].y);
                    mma4(c[mf][2 * np + 1], af[mf], bf[np].z, bf[np].w);
                }
        }
    }

    // epilogue: add bias, write fp32
    const int gr = lane >> 2, tg = lane & 3;
#pragma unroll
    for (int mf = 0; mf < 4; mf++) {
        const int row = bm * BM + wm * 64 + mf * 16 + gr;
#pragma unroll
        for (int nf = 0; nf < 8; nf++) {
            const int col = bn * BN + wn * 64 + (nf >> 1) * 16 + (nf & 1) * 8 + tg * 2;
            const float b0 = __ldg(&bias[col]);
            const float b1 = __ldg(&bias[col + 1]);
            float2 v0 = make_float2(c[mf][nf][0] + b0, c[mf][nf][1] + b1);
            float2 v1 = make_float2(c[mf][nf][2] + b0, c[mf][nf][3] + b1);
            *(float2*)&out[(size_t)row * N_OUT + col] = v0;
            *(float2*)&out[(size_t)(row + 8) * N_OUT + col] = v1;
        }
    }
}

// ---------------------------------------------------------------------------
extern "C" void kernel_launch(void* const* d_in, const int* in_sizes, int n_in,
                              void* d_out, int out_size) {
    const float* x    = (const float*)d_in[0];
    const float* W    = (const float*)d_in[1];
    const float* bias = (const float*)d_in[2];
    const float* A    = (const float*)d_in[3];
    const float* Bm   = (const float*)d_in[4];
    float* out = (float*)d_out;

    cudaFuncSetAttribute(gemm_kernel, cudaFuncAttributeMaxDynamicSharedMemorySize,
                         NSTAGE * STAGE_BYTES);

    cvt_x_kernel<<<16384, 256>>>((const float4*)x);
    cvt_w_kernel<<<4096, 256>>>((const float4*)W);
    cvt_b_kernel<<<64, 256>>>((const float4*)Bm);
    z_partial<<<dim3(128, 4), 128>>>(x, A);
    topk_kernel<<<4096, 256>>>();
    gemm_kernel<<<GRID_TILES, 256, NSTAGE * STAGE_BYTES>>>(bias, out);
}

// round 13
// speedup vs baseline: 1.9782x; 1.6506x over previous
#include <cuda_runtime.h>
#include <cuda_bf16.h>
#include <cuda_fp16.h>
#include <cstdint>

// Problem constants
#define M_ROWS 16384          // B_SZ * SEQ
#define K_IN   4096           // D_IN
#define N_OUT  4096           // D_OUT
#define R_LORA 64
#define K_TOP  16
#define K_EXT  4160           // K_IN + R_LORA
#define SCALE_F 2.0f          // ALPHA / R
#define KB16   (K_EXT / 16)   // 260 k-blocks of 16

// GEMM tiling
#define BM 128
#define BN 256
#define NSTAGE 5
#define KTILES (K_EXT / 32)        // 130 (two kb16 per ktile)
#define A_ST_BYTES 8192            // 8 mt * 2 kb * 512B
#define B_ST_BYTES 16384           // 16 nt * 2 kb * 512B
#define STAGE_BYTES (A_ST_BYTES + B_ST_BYTES)   // 24576
#define GRID_TILES ((M_ROWS / BM) * (N_OUT / BN))   // 128*16 = 2048

// Scratch (device globals: allocation-free), fp16 fragment-major.
// g_xa: A' [mt(1024)][kb16(260)][lane(32)] uint4 = {a0,a1,a2,a3} of m16n8k16:
//   a0={A[gr][2tg],A[gr][2tg+1]} a1={A[gr+8][2tg..]} a2={A[gr][2tg+8..]} a3={A[gr+8][2tg+8..]}
// g_wb: B' [nt16(256)][kb16(260)][lane] uint4 = {b0,b1 of n8-block0, b0,b1 of n8-block1}:
//   q0={W[gr][2tg..]} q1={W[gr][2tg+8..]} q2={W[gr+8][2tg..]} q3={W[gr+8][2tg+8..]}
__device__ __half g_xa[(size_t)M_ROWS * K_EXT];
__device__ __half g_wb[(size_t)N_OUT * K_EXT];
__device__ float  g_zp[4ull * M_ROWS * R_LORA];   // split-K partials of z (fp32)

__device__ __forceinline__ uint32_t packh2(float lo, float hi) {
    __half2 h = __floats2half2_rn(lo, hi);
    return *(uint32_t*)&h;
}

// ---------------------------------------------------------------------------
// cvt_x: fp32 x -> fp16 fragment-major A' (k < 4096).  block = mt x 256k.
// ---------------------------------------------------------------------------
__global__ __launch_bounds__(256) void cvt_x_kernel(const float4* __restrict__ in) {
    __shared__ float s[16][260];
    const int t  = threadIdx.x;
    const int mt = blockIdx.x >> 4;
    const int kc = blockIdx.x & 15;

#pragma unroll
    for (int p = 0; p < 4; p++) {
        int idx = t + p * 256;              // 0..1023
        int row = idx >> 6;                 // 0..15
        int kq  = idx & 63;
        float4 v = in[((size_t)(mt * 16 + row) * K_IN + kc * 256) / 4 + kq];
        s[row][kq * 4 + 0] = v.x; s[row][kq * 4 + 1] = v.y;
        s[row][kq * 4 + 2] = v.z; s[row][kq * 4 + 3] = v.w;
    }
    __syncthreads();

    uint4* g4 = (uint4*)g_xa;
#pragma unroll
    for (int p = 0; p < 2; p++) {
        int idx  = t + p * 256;             // 0..511
        int kbl  = idx >> 5;                // 0..15
        int lane = idx & 31;
        int gr = lane >> 2, tg = lane & 3;
        int kk = kbl * 16;
        uint4 v;
        v.x = packh2(s[gr    ][kk + 2 * tg    ], s[gr    ][kk + 2 * tg + 1]);
        v.y = packh2(s[gr + 8][kk + 2 * tg    ], s[gr + 8][kk + 2 * tg + 1]);
        v.z = packh2(s[gr    ][kk + 2 * tg + 8], s[gr    ][kk + 2 * tg + 9]);
        v.w = packh2(s[gr + 8][kk + 2 * tg + 8], s[gr + 8][kk + 2 * tg + 9]);
        g4[((size_t)mt * KB16 + kc * 16 + kbl) * 32 + lane] = v;
    }
}

// ---------------------------------------------------------------------------
// cvt_w: fp32 W -> fp16 fragment-major B' (k < 4096).  block = nt16 x 256k.
// ---------------------------------------------------------------------------
__global__ __launch_bounds__(256) void cvt_w_kernel(const float4* __restrict__ in) {
    __shared__ float s[16][260];
    const int t  = threadIdx.x;
    const int nt = blockIdx.x >> 4;
    const int kc = blockIdx.x & 15;

#pragma unroll
    for (int p = 0; p < 4; p++) {
        int idx = t + p * 256;
        int row = idx >> 6;
        int kq  = idx & 63;
        float4 v = in[((size_t)(nt * 16 + row) * K_IN + kc * 256) / 4 + kq];
        s[row][kq * 4 + 0] = v.x; s[row][kq * 4 + 1] = v.y;
        s[row][kq * 4 + 2] = v.z; s[row][kq * 4 + 3] = v.w;
    }
    __syncthreads();

    uint4* g4 = (uint4*)g_wb;
#pragma unroll
    for (int p = 0; p < 2; p++) {
        int idx  = t + p * 256;
        int kbl  = idx >> 5;
        int lane = idx & 31;
        int gr = lane >> 2, tg = lane & 3;
        int kk = kbl * 16;
        uint4 v;
        v.x = packh2(s[gr    ][kk + 2 * tg    ], s[gr    ][kk + 2 * tg + 1]);
        v.y = packh2(s[gr    ][kk + 2 * tg + 8], s[gr    ][kk + 2 * tg + 9]);
        v.z = packh2(s[gr + 8][kk + 2 * tg    ], s[gr + 8][kk + 2 * tg + 1]);
        v.w = packh2(s[gr + 8][kk + 2 * tg + 8], s[gr + 8][kk + 2 * tg + 9]);
        g4[((size_t)nt * KB16 + kc * 16 + kbl) * 32 + lane] = v;
    }
}

// ---------------------------------------------------------------------------
// cvt_b: LoRA B (4096 x 64) -> fp16 B' extension (kb16 256..259).
// block = 64 n-rows (4 nt16) x 64 r.  grid = 64.
// ---------------------------------------------------------------------------
__global__ __launch_bounds__(256) void cvt_b_kernel(const float4* __restrict__ in) {
    __shared__ float s[64][68];
    const int t   = threadIdx.x;
    const int n0t = blockIdx.x * 4;     // first nt16 tile

#pragma unroll
    for (int p = 0; p < 4; p++) {
        int idx = t + p * 256;          // 0..1023 float4s (64 rows x 16)
        int row = idx >> 4;
        int kq  = idx & 15;
        float4 v = in[((size_t)(n0t * 16 + row) * R_LORA) / 4 + kq];
        s[row][kq * 4 + 0] = v.x; s[row][kq * 4 + 1] = v.y;
        s[row][kq * 4 + 2] = v.z; s[row][kq * 4 + 3] = v.w;
    }
    __syncthreads();

    uint4* g4 = (uint4*)g_wb;
#pragma unroll
    for (int p = 0; p < 2; p++) {
        int idx  = t + p * 256;         // 0..511
        int blk  = idx >> 5;            // 0..15 = ntl*4 + kbl
        int ntl  = blk >> 2;
        int kbl  = blk & 3;
        int lane = idx & 31;
        int gr = lane >> 2, tg = lane & 3;
        int r0 = ntl * 16;
        int kk = kbl * 16;
        uint4 v;
        v.x = packh2(s[r0 + gr    ][kk + 2 * tg    ], s[r0 + gr    ][kk + 2 * tg + 1]);
        v.y = packh2(s[r0 + gr    ][kk + 2 * tg + 8], s[r0 + gr    ][kk + 2 * tg + 9]);
        v.z = packh2(s[r0 + gr + 8][kk + 2 * tg    ], s[r0 + gr + 8][kk + 2 * tg + 1]);
        v.w = packh2(s[r0 + gr + 8][kk + 2 * tg + 8], s[r0 + gr + 8][kk + 2 * tg + 9]);
        g4[((size_t)(n0t + ntl) * KB16 + 256 + kbl) * 32 + lane] = v;
    }
}

// ---------------------------------------------------------------------------
// z = x @ A^T in fp32 (accuracy needed for correct top-k selection).
// Split-K=4, deterministic partial buffers.
// ---------------------------------------------------------------------------
__global__ __launch_bounds__(128) void z_partial(const float* __restrict__ x,
                                                 const float* __restrict__ Amat) {
    __shared__ float xsT[32][132];
    __shared__ float asT[32][68];

    const int t  = threadIdx.x;
    const int m0 = blockIdx.x * 128;
    const int kb = blockIdx.y * 1024;
    const int tm = t >> 3;
    const int tr = t & 7;

    float acc[8][8];
#pragma unroll
    for (int i = 0; i < 8; i++)
#pragma unroll
        for (int j = 0; j < 8; j++) acc[i][j] = 0.0f;

    for (int kc = 0; kc < 1024; kc += 32) {
        const int k0 = kb + kc;
        const int kk0 = (t & 7) << 2;
#pragma unroll
        for (int i = 0; i < 8; i++) {
            int r = (t >> 3) + i * 16;
            float4 v = *(const float4*)&x[(size_t)(m0 + r) * K_IN + k0 + kk0];
            xsT[kk0 + 0][r] = v.x; xsT[kk0 + 1][r] = v.y;
            xsT[kk0 + 2][r] = v.z; xsT[kk0 + 3][r] = v.w;
        }
#pragma unroll
        for (int i = 0; i < 4; i++) {
            int r = (t >> 3) + i * 16;
            float4 v = *(const float4*)&Amat[(size_t)r * K_IN + k0 + kk0];
            asT[kk0 + 0][r] = v.x; asT[kk0 + 1][r] = v.y;
            asT[kk0 + 2][r] = v.z; asT[kk0 + 3][r] = v.w;
        }
        __syncthreads();
#pragma unroll
        for (int kk = 0; kk < 32; kk++) {
            float av[8], bv[8];
            *(float4*)&av[0] = *(const float4*)&xsT[kk][tm * 8];
            *(float4*)&av[4] = *(const float4*)&xsT[kk][tm * 8 + 4];
            *(float4*)&bv[0] = *(const float4*)&asT[kk][tr * 8];
            *(float4*)&bv[4] = *(const float4*)&asT[kk][tr * 8 + 4];
#pragma unroll
            for (int i = 0; i < 8; i++)
#pragma unroll
                for (int j = 0; j < 8; j++)
                    acc[i][j] = fmaf(av[i], bv[j], acc[i][j]);
        }
        __syncthreads();
    }

    float* zp = g_zp + (size_t)blockIdx.y * M_ROWS * R_LORA;
#pragma unroll
    for (int i = 0; i < 8; i++)
#pragma unroll
        for (int j = 0; j < 8; j++)
            zp[(size_t)(m0 + tm * 8 + i) * R_LORA + tr * 8 + j] = acc[i][j];
}

// ---------------------------------------------------------------------------
// Top-k (k=16 of 64): keep iff #{j: az_j > az_i} < 16.
// Writes SCALE*z (fp16) into the fragment-major extension block of g_xa.
// ---------------------------------------------------------------------------
__global__ void topk_kernel() {
    __shared__ float az[4][64];
    const int sub = threadIdx.x >> 6;
    const int j   = threadIdx.x & 63;
    const int row = blockIdx.x * 4 + sub;

    const size_t ZP = (size_t)M_ROWS * R_LORA;
    const size_t base = (size_t)row * R_LORA + j;
    float v = ((g_zp[base] + g_zp[base + ZP]) + g_zp[base + 2 * ZP]) + g_zp[base + 3 * ZP];
    float a = fabsf(v);
    az[sub][j] = a;
    __syncthreads();

    int cnt = 0;
#pragma unroll
    for (int t = 0; t < 64; t++) cnt += (az[sub][t] > a) ? 1 : 0;

    // fragment-major fp16 address within g_xa (A' layout, m16n8k16)
    const int mt = row >> 4, mr = row & 15;
    const int kb = 256 + (j >> 4);
    const int kl = j & 15;
    const int gr = mr & 7;
    const int tg = (kl & 7) >> 1;
    const int q  = ((kl >> 3) << 1) + (mr >> 3);
    const int lane = gr * 4 + tg;
    size_t idx = ((((size_t)mt * KB16 + kb) * 32 + lane) << 3) + (q << 1) + (kl & 1);
    g_xa[idx] = __float2half_rn((cnt < K_TOP) ? v * SCALE_F : 0.0f);
}

// ---------------------------------------------------------------------------
// Main GEMM: out[m,n] = sum_k x*w + bias.  fp16 mma.sync m16n8k16, fp32 accum.
// CTA 128x256x32, warp tile 64x64, fragment-major smem, LDS.128 only.
// ---------------------------------------------------------------------------
__device__ __forceinline__ void cp_async16(uint32_t smem_addr, const void* gptr) {
    asm volatile("cp.async.cg.shared.global [%0], [%1], 16;\n"
                 :: "r"(smem_addr), "l"(gptr));
}

__device__ __forceinline__ void mma_h(float* c, const uint4& a, uint32_t b0, uint32_t b1) {
    asm volatile(
        "mma.sync.aligned.m16n8k16.row.col.f32.f16.f16.f32 "
        "{%0,%1,%2,%3}, {%4,%5,%6,%7}, {%8,%9}, {%0,%1,%2,%3};\n"
        : "+f"(c[0]), "+f"(c[1]), "+f"(c[2]), "+f"(c[3])
        : "r"(a.x), "r"(a.y), "r"(a.z), "r"(a.w), "r"(b0), "r"(b1));
}

__global__ __launch_bounds__(256, 1) void gemm_kernel(const float* __restrict__ bias,
                                                      float* __restrict__ out) {
    extern __shared__ uint4 sm4[];

    const int t    = threadIdx.x;
    const int lane = t & 31;
    const int wid  = t >> 5;
    const int wm   = wid & 1;          // 2 warps in m (64 rows each)
    const int wn   = wid >> 1;         // 4 warps in n (64 cols each)

    // L2-friendly rasterization: supertiles of 8 bm x 16 bn
    const int pid = blockIdx.x;
    const int grp = pid >> 7;                // 0..15
    const int loc = pid & 127;
    const int bm  = grp * 8 + (loc & 7);     // 0..127
    const int bn  = loc >> 3;                // 0..15

    const uint4* gA = (const uint4*)g_xa;
    const uint4* gB = (const uint4*)g_wb;
    const uint32_t sbase = (uint32_t)__cvta_generic_to_shared(sm4);

    // per-thread cp.async descriptors (uint4 index at kt=0, smem byte offset)
    size_t aG[2]; uint32_t aS[2];
#pragma unroll
    for (int i = 0; i < 2; i++) {
        int ia   = t + i * 256;              // 0..511
        int blk  = ia >> 5;                  // mtl*2 + kbl
        int lc   = ia & 31;
        int mtl  = blk >> 1, kbl = blk & 1;
        aG[i] = ((size_t)(bm * 8 + mtl) * KB16 + kbl) * 32 + lc;
        aS[i] = (uint32_t)(ia * 16);
    }
    size_t bG[4]; uint32_t bS[4];
#pragma unroll
    for (int i = 0; i < 4; i++) {
        int ib   = t + i * 256;              // 0..1023
        int blk  = ib >> 5;                  // ntl*2 + kbl
        int lc   = ib & 31;
        int ntl  = blk >> 1, kbl = blk & 1;
        bG[i] = ((size_t)(bn * 16 + ntl) * KB16 + kbl) * 32 + lc;
        bS[i] = (uint32_t)(A_ST_BYTES + ib * 16);
    }

    // prologue: stages 0..NSTAGE-2
#pragma unroll
    for (int s = 0; s < NSTAGE - 1; s++) {
        uint32_t so = sbase + s * STAGE_BYTES;
#pragma unroll
        for (int i = 0; i < 2; i++) cp_async16(so + aS[i], gA + aG[i] + (size_t)s * 64);
#pragma unroll
        for (int i = 0; i < 4; i++) cp_async16(so + bS[i], gB + bG[i] + (size_t)s * 64);
        asm volatile("cp.async.commit_group;\n");
    }

    float c[4][8][4];
#pragma unroll
    for (int mf = 0; mf < 4; mf++)
#pragma unroll
        for (int nf = 0; nf < 8; nf++)
#pragma unroll
            for (int q = 0; q < 4; q++) c[mf][nf][q] = 0.0f;

    for (int kt = 0; kt < KTILES; kt++) {
        asm volatile("cp.async.wait_group 3;\n");
        __syncthreads();

        const int kf = kt + NSTAGE - 1;
        if (kf < KTILES) {
            uint32_t so = sbase + (kf % NSTAGE) * STAGE_BYTES;
#pragma unroll
            for (int i = 0; i < 2; i++) cp_async16(so + aS[i], gA + aG[i] + (size_t)kf * 64);
#pragma unroll
            for (int i = 0; i < 4; i++) cp_async16(so + bS[i], gB + bG[i] + (size_t)kf * 64);
        }
        asm volatile("cp.async.commit_group;\n");

        const uint4* As4 = sm4 + (size_t)(kt % NSTAGE) * (STAGE_BYTES / 16);
        const uint4* Bs4 = As4 + (A_ST_BYTES / 16);

#pragma unroll
        for (int kbl = 0; kbl < 2; kbl++) {
            uint4 af[4], bf[4];
#pragma unroll
            for (int mf = 0; mf < 4; mf++)
                af[mf] = As4[((wm * 4 + mf) * 2 + kbl) * 32 + lane];
#pragma unroll
            for (int np = 0; np < 4; np++)
                bf[np] = Bs4[((wn * 4 + np) * 2 + kbl) * 32 + lane];
#pragma unroll
            for (int mf = 0; mf < 4; mf++)
#pragma unroll
                for (int np = 0; np < 4; np++) {
                    mma_h(c[mf][2 * np],     af[mf], bf[np].x, bf[np].y);
                    mma_h(c[mf][2 * np + 1], af[mf], bf[np].z, bf[np].w);
                }
        }
    }

    // epilogue: add bias, write fp32
    const int gr = lane >> 2, tg = lane & 3;
#pragma unroll
    for (int mf = 0; mf < 4; mf++) {
        const int row = bm * BM + wm * 64 + mf * 16 + gr;
#pragma unroll
        for (int nf = 0; nf < 8; nf++) {
            const int col = bn * BN + wn * 64 + (nf >> 1) * 16 + (nf & 1) * 8 + tg * 2;
            const float b0 = __ldg(&bias[col]);
            const float b1 = __ldg(&bias[col + 1]);
            float2 v0 = make_float2(c[mf][nf][0] + b0, c[mf][nf][1] + b1);
            float2 v1 = make_float2(c[mf][nf][2] + b0, c[mf][nf][3] + b1);
            *(float2*)&out[(size_t)row * N_OUT + col] = v0;
            *(float2*)&out[(size_t)(row + 8) * N_OUT + col] = v1;
        }
    }
}

// ---------------------------------------------------------------------------
extern "C" void kernel_launch(void* const* d_in, const int* in_sizes, int n_in,
                              void* d_out, int out_size) {
    const float* x    = (const float*)d_in[0];
    const float* W    = (const float*)d_in[1];
    const float* bias = (const float*)d_in[2];
    const float* A    = (const float*)d_in[3];
    const float* Bm   = (const float*)d_in[4];
    float* out = (float*)d_out;

    cudaFuncSetAttribute(gemm_kernel, cudaFuncAttributeMaxDynamicSharedMemorySize,
                         NSTAGE * STAGE_BYTES);

    cvt_x_kernel<<<16384, 256>>>((const float4*)x);
    cvt_w_kernel<<<4096, 256>>>((const float4*)W);
    cvt_b_kernel<<<64, 256>>>((const float4*)Bm);
    z_partial<<<dim3(128, 4), 128>>>(x, A);
    topk_kernel<<<4096, 256>>>();
    gemm_kernel<<<GRID_TILES, 256, NSTAGE * STAGE_BYTES>>>(bias, out);
}